// round 2
// baseline (speedup 1.0000x reference)
#include <cuda_runtime.h>
#include <cstddef>
#include <cstdint>

#define NN   10000
#define INDIM 256
#define HID  64

// ---------------- static scratch (no allocations allowed) --------------------
__device__ __align__(256) float d_scratch[5900000];

// float-index offsets into d_scratch
#define OFF_B0    0        // [NN,64] x@W1
#define OFF_H1    640000   // relu(A@B0+b1)
#define OFF_Q     1280000  // A@H1
#define OFF_H     1920000  // Q@W2+b2
#define OFF_R     2560000  // A@H
#define OFF_X1    3200000  // relu(R@Wa1+ba1)
#define OFF_S     3840000  // A@X1
#define OFF_P     4480000  // R@G
#define OFF_EPACK 5120000  // float2[320000] {src_bits, norm}
#define OFF_G     5760000  // [64,64]
#define OFF_V     5764096  // [64]
#define OFF_BB    5764160  // [1]
#define OFF_C     5764224  // [NN] c' = R@v + bb/2
#define OFF_DINV  5774224  // [NN]
#define OFF_SELFC 5784224  // [NN]
#define OFF_OFFS  5794224  // int[NN+1]
#define OFF_CUR   5804240  // int[NN]
#define OFF_CNT   5814240  // int[NN]
#define OFF_FLAG  5824240  // int[1]: 1 if edge_index is int64

// ---------------- f32x2 helpers ----------------------------------------------
__device__ __forceinline__ unsigned long long splat2(float a) {
    unsigned long long r;
    asm("mov.b64 %0, {%1, %1};" : "=l"(r) : "f"(a));
    return r;
}
__device__ __forceinline__ unsigned long long fma2(unsigned long long a,
                                                   unsigned long long b,
                                                   unsigned long long c) {
    unsigned long long d;
    asm("fma.rn.f32x2 %0, %1, %2, %3;" : "=l"(d) : "l"(a), "l"(b), "l"(c));
    return d;
}
__device__ __forceinline__ void unpack2(unsigned long long v, float& x, float& y) {
    asm("mov.b64 {%0, %1}, %2;" : "=f"(x), "=f"(y) : "l"(v));
}

// ---------------- graph build --------------------------------------------------
__global__ void k_detect(const void* ei, int* flag) {
    __shared__ int cnt;
    if (threadIdx.x == 0) cnt = 0;
    __syncthreads();
    long long v = ((const long long*)ei)[threadIdx.x];  // reads first 2KB, safe either way
    if (v >= 0 && v < NN) atomicAdd(&cnt, 1);
    __syncthreads();
    if (threadIdx.x == 0) *flag = (cnt > 128) ? 1 : 0;
}

__global__ void k_zero(int* cnt, int n) {
    int i = blockIdx.x * blockDim.x + threadIdx.x;
    if (i < n) cnt[i] = 0;
}

__global__ void k_hist(const void* ei, int E, const int* __restrict__ flag,
                       int* __restrict__ cnt) {
    int e = blockIdx.x * blockDim.x + threadIdx.x;
    if (e >= E) return;
    int s, d;
    if (*flag) {
        const long long* p = (const long long*)ei;
        s = (int)p[e]; d = (int)p[E + e];
    } else {
        const int* p = (const int*)ei;
        s = p[e]; d = p[E + e];
    }
    if (s != d) atomicAdd(&cnt[d], 1);
}

__global__ void k_scan(const int* __restrict__ cnt, int* __restrict__ offs,
                       int* __restrict__ cur, float* __restrict__ dinv,
                       float* __restrict__ selfc, int n) {
    const int IT = 10;
    __shared__ int wsum[32];
    int tid = threadIdx.x;
    int base = tid * IT;
    int loc[IT];
    int s = 0;
#pragma unroll
    for (int k = 0; k < IT; k++) {
        int idx = base + k;
        int v = (idx < n) ? cnt[idx] : 0;
        loc[k] = s;
        s += v;
        if (idx < n) {
            float dg = (float)(v + 1);
            dinv[idx] = rsqrtf(dg);
            selfc[idx] = 1.0f / dg;
        }
    }
    int lane = tid & 31, wid = tid >> 5;
    int x = s;
#pragma unroll
    for (int o = 1; o < 32; o <<= 1) {
        int y = __shfl_up_sync(0xffffffffu, x, o);
        if (lane >= o) x += y;
    }
    if (lane == 31) wsum[wid] = x;
    __syncthreads();
    if (wid == 0) {
        int y = wsum[lane];
#pragma unroll
        for (int o = 1; o < 32; o <<= 1) {
            int z = __shfl_up_sync(0xffffffffu, y, o);
            if (lane >= o) y += z;
        }
        wsum[lane] = y;
    }
    __syncthreads();
    int pre = x - s + (wid ? wsum[wid - 1] : 0);
#pragma unroll
    for (int k = 0; k < IT; k++) {
        int idx = base + k;
        if (idx < n) { offs[idx] = pre + loc[k]; cur[idx] = pre + loc[k]; }
        else if (idx == n) { offs[n] = pre + loc[k]; }
    }
}

__global__ void k_scatter(const void* ei, int E, const int* __restrict__ flag,
                          const float* __restrict__ dinv, int* __restrict__ cur,
                          float2* __restrict__ epack) {
    int e = blockIdx.x * blockDim.x + threadIdx.x;
    if (e >= E) return;
    int s, d;
    if (*flag) {
        const long long* p = (const long long*)ei;
        s = (int)p[e]; d = (int)p[E + e];
    } else {
        const int* p = (const int*)ei;
        s = p[e]; d = p[E + e];
    }
    if (s != d) {
        int pos = atomicAdd(&cur[d], 1);
        epack[pos] = make_float2(__int_as_float(s), dinv[s] * dinv[d]);
    }
}

// ---------------- GCN propagation: out = A_norm @ y (+bias)(+relu), dim=64 ----
__global__ void k_prop(const float* __restrict__ y, float* __restrict__ out,
                       const float2* __restrict__ ep, const int* __restrict__ offs,
                       const float* __restrict__ selfc, const float* __restrict__ bias,
                       int relu, int n) {
    int w = (blockIdx.x * blockDim.x + threadIdx.x) >> 5;
    int lane = threadIdx.x & 31;
    if (w >= n) return;
    const float2* Y = (const float2*)y;
    float sc = selfc[w];
    float2 yd = Y[w * 32 + lane];
    float ax = sc * yd.x, ay = sc * yd.y;
    int e = offs[w], e1 = offs[w + 1];
    for (; e + 1 < e1; e += 2) {
        float2 p0 = ep[e], p1 = ep[e + 1];
        float2 y0 = Y[__float_as_int(p0.x) * 32 + lane];
        float2 y1 = Y[__float_as_int(p1.x) * 32 + lane];
        ax = fmaf(p0.y, y0.x, ax); ay = fmaf(p0.y, y0.y, ay);
        ax = fmaf(p1.y, y1.x, ax); ay = fmaf(p1.y, y1.y, ay);
    }
    if (e < e1) {
        float2 p0 = ep[e];
        float2 y0 = Y[__float_as_int(p0.x) * 32 + lane];
        ax = fmaf(p0.y, y0.x, ax); ay = fmaf(p0.y, y0.y, ay);
    }
    if (bias) {
        float2 b = ((const float2*)bias)[lane];
        ax += b.x; ay += b.y;
    }
    if (relu) { ax = fmaxf(ax, 0.f); ay = fmaxf(ay, 0.f); }
    ((float2*)out)[w * 32 + lane] = make_float2(ax, ay);
}

// ---------------- small GEMM: C[M,N] = A[M,K] @ W[K,N] (+bias)(+relu) ----------
__global__ __launch_bounds__(256) void k_gemm(
    const float* __restrict__ A, const float* __restrict__ W,
    const float* __restrict__ bias, float* __restrict__ C,
    int M, int N, int K, int relu) {
    __shared__ float As[16][68];
    __shared__ float Ws[16][68];
    int tid = threadIdx.x;
    int row0 = blockIdx.y * 64, col0 = blockIdx.x * 64;
    int tx = tid & 15, ty = tid >> 4;
    int lr = tid >> 2, lq = tid & 3;   // A loader
    int wr = tid >> 4, wc = tid & 15;  // W loader
    float acc[4][4];
#pragma unroll
    for (int i = 0; i < 4; i++)
#pragma unroll
        for (int j = 0; j < 4; j++) acc[i][j] = 0.f;

    for (int k0 = 0; k0 < K; k0 += 16) {
        int ar = min(row0 + lr, M - 1);
        float4 av = *(const float4*)&A[(size_t)ar * K + k0 + 4 * lq];
        As[4 * lq + 0][lr] = av.x; As[4 * lq + 1][lr] = av.y;
        As[4 * lq + 2][lr] = av.z; As[4 * lq + 3][lr] = av.w;
        float4 wv = *(const float4*)&W[(size_t)(k0 + wr) * N + col0 + 4 * wc];
        *(float4*)&Ws[wr][4 * wc] = wv;
        __syncthreads();
#pragma unroll
        for (int k = 0; k < 16; k++) {
            float4 a = *(float4*)&As[k][ty * 4];
            float4 b = *(float4*)&Ws[k][tx * 4];
            acc[0][0] = fmaf(a.x, b.x, acc[0][0]); acc[0][1] = fmaf(a.x, b.y, acc[0][1]);
            acc[0][2] = fmaf(a.x, b.z, acc[0][2]); acc[0][3] = fmaf(a.x, b.w, acc[0][3]);
            acc[1][0] = fmaf(a.y, b.x, acc[1][0]); acc[1][1] = fmaf(a.y, b.y, acc[1][1]);
            acc[1][2] = fmaf(a.y, b.z, acc[1][2]); acc[1][3] = fmaf(a.y, b.w, acc[1][3]);
            acc[2][0] = fmaf(a.z, b.x, acc[2][0]); acc[2][1] = fmaf(a.z, b.y, acc[2][1]);
            acc[2][2] = fmaf(a.z, b.z, acc[2][2]); acc[2][3] = fmaf(a.z, b.w, acc[2][3]);
            acc[3][0] = fmaf(a.w, b.x, acc[3][0]); acc[3][1] = fmaf(a.w, b.y, acc[3][1]);
            acc[3][2] = fmaf(a.w, b.z, acc[3][2]); acc[3][3] = fmaf(a.w, b.w, acc[3][3]);
        }
        __syncthreads();
    }
    float4 bv = make_float4(0.f, 0.f, 0.f, 0.f);
    if (bias) bv = *(const float4*)&bias[col0 + tx * 4];
#pragma unroll
    for (int i = 0; i < 4; i++) {
        int gr = row0 + ty * 4 + i;
        if (gr < M) {
            float4 o;
            o.x = acc[i][0] + bv.x; o.y = acc[i][1] + bv.y;
            o.z = acc[i][2] + bv.z; o.w = acc[i][3] + bv.w;
            if (relu) {
                o.x = fmaxf(o.x, 0.f); o.y = fmaxf(o.y, 0.f);
                o.z = fmaxf(o.z, 0.f); o.w = fmaxf(o.w, 0.f);
            }
            *(float4*)&C[(size_t)gr * N + col0 + tx * 4] = o;
        }
    }
}

// ---------------- G = Ws Ws^T, v = Ws bs, bb = bs.bs ---------------------------
__global__ void k_gram(const float* __restrict__ Ws, const float* __restrict__ bs,
                       float* __restrict__ G, float* __restrict__ v, float* __restrict__ bb) {
    int idx = blockIdx.x * blockDim.x + threadIdx.x;
    if (idx < 4096) {
        int i = idx >> 6, j = idx & 63;
        const float4* a = (const float4*)(Ws + i * 256);
        const float4* b = (const float4*)(Ws + j * 256);
        float s = 0.f;
#pragma unroll 8
        for (int k = 0; k < 64; k++) {
            float4 x = __ldg(&a[k]), y = __ldg(&b[k]);
            s += x.x * y.x + x.y * y.y + x.z * y.z + x.w * y.w;
        }
        G[idx] = s;
        if (j == 0) {  // also compute v[i]
            const float4* c = (const float4*)bs;
            float t = 0.f;
#pragma unroll 8
            for (int k = 0; k < 64; k++) {
                float4 x = __ldg(&a[k]), y = __ldg(&c[k]);
                t += x.x * y.x + x.y * y.y + x.z * y.z + x.w * y.w;
            }
            v[i] = t;
        }
        if (idx == 0) {
            const float4* c = (const float4*)bs;
            float t = 0.f;
#pragma unroll 8
            for (int k = 0; k < 64; k++) {
                float4 y = __ldg(&c[k]);
                t += y.x * y.x + y.y * y.y + y.z * y.z + y.w * y.w;
            }
            bb[0] = t;
        }
    }
}

// ---------------- c'[i] = R[i].v + bb/2 ---------------------------------------
__global__ void k_c(const float* __restrict__ R, const float* __restrict__ v,
                    const float* __restrict__ bb, float* __restrict__ c, int n) {
    int w = (blockIdx.x * blockDim.x + threadIdx.x) >> 5;
    int lane = threadIdx.x & 31;
    if (w >= n) return;
    float2 r2 = ((const float2*)R)[w * 32 + lane];
    float2 v2 = ((const float2*)v)[lane];
    float s = r2.x * v2.x + r2.y * v2.y;
#pragma unroll
    for (int o = 16; o; o >>= 1) s += __shfl_xor_sync(0xffffffffu, s, o);
    if (lane == 0) c[w] = s + 0.5f * bb[0];
}

// ---------------- adj = P @ R^T + c_i + c_j (128x128 tiles, K=64, f32x2) -------
__global__ __launch_bounds__(256) void k_adj(
    const float* __restrict__ P, const float* __restrict__ R,
    const float* __restrict__ c, float* __restrict__ adj, int n) {
    extern __shared__ float sm[];
    float* Ps = sm;              // [64][128] k-major
    float* Rs = sm + 64 * 128;   // [64][128]
    int row0 = blockIdx.y * 128, col0 = blockIdx.x * 128;
    int tid = threadIdx.x;

    // conflict-free transpose load: lane owns one row, warps span 32 rows
    {
        int rr = tid & 127, half = tid >> 7;
        const float4* P4 = (const float4*)P;
        const float4* R4 = (const float4*)R;
        int prow = min(row0 + rr, n - 1);
        int rrow = min(col0 + rr, n - 1);
#pragma unroll
        for (int i = 0; i < 8; i++) {
            int c4 = half * 8 + i;
            float4 pv = P4[(size_t)prow * 16 + c4];
            float4 rv = R4[(size_t)rrow * 16 + c4];
            Ps[(4 * c4 + 0) * 128 + rr] = pv.x; Ps[(4 * c4 + 1) * 128 + rr] = pv.y;
            Ps[(4 * c4 + 2) * 128 + rr] = pv.z; Ps[(4 * c4 + 3) * 128 + rr] = pv.w;
            Rs[(4 * c4 + 0) * 128 + rr] = rv.x; Rs[(4 * c4 + 1) * 128 + rr] = rv.y;
            Rs[(4 * c4 + 2) * 128 + rr] = rv.z; Rs[(4 * c4 + 3) * 128 + rr] = rv.w;
        }
    }
    __syncthreads();

    int tx = tid & 15, ty = tid >> 4;
    unsigned long long acc[32];
#pragma unroll
    for (int i = 0; i < 32; i++) acc[i] = 0ull;

#pragma unroll 8
    for (int k = 0; k < 64; k++) {
        float4 a0 = *(float4*)&Ps[k * 128 + ty * 8];
        float4 a1 = *(float4*)&Ps[k * 128 + ty * 8 + 4];
        float4 b0 = *(float4*)&Rs[k * 128 + tx * 8];
        float4 b1 = *(float4*)&Rs[k * 128 + tx * 8 + 4];
        unsigned long long bp0, bp1, bp2, bp3;
        asm("mov.b64 %0, {%1, %2};" : "=l"(bp0) : "f"(b0.x), "f"(b0.y));
        asm("mov.b64 %0, {%1, %2};" : "=l"(bp1) : "f"(b0.z), "f"(b0.w));
        asm("mov.b64 %0, {%1, %2};" : "=l"(bp2) : "f"(b1.x), "f"(b1.y));
        asm("mov.b64 %0, {%1, %2};" : "=l"(bp3) : "f"(b1.z), "f"(b1.w));
        float ar[8] = {a0.x, a0.y, a0.z, a0.w, a1.x, a1.y, a1.z, a1.w};
#pragma unroll
        for (int i = 0; i < 8; i++) {
            unsigned long long as = splat2(ar[i]);
            acc[i * 4 + 0] = fma2(as, bp0, acc[i * 4 + 0]);
            acc[i * 4 + 1] = fma2(as, bp1, acc[i * 4 + 1]);
            acc[i * 4 + 2] = fma2(as, bp2, acc[i * 4 + 2]);
            acc[i * 4 + 3] = fma2(as, bp3, acc[i * 4 + 3]);
        }
    }

    // epilogue: + c_i + c_j (c already includes bb/2 each)
    int gcb = col0 + tx * 8;
    if (gcb >= n) return;
    float cj[8];
#pragma unroll
    for (int j = 0; j < 8; j++) cj[j] = __ldg(&c[min(gcb + j, n - 1)]);
#pragma unroll
    for (int ii = 0; ii < 8; ii++) {
        int gr = row0 + ty * 8 + ii;
        if (gr < n) {
            float ci = __ldg(&c[gr]);
            float o[8];
#pragma unroll
            for (int p = 0; p < 4; p++) {
                float x, y;
                unpack2(acc[ii * 4 + p], x, y);
                o[2 * p] = x + ci + cj[2 * p];
                o[2 * p + 1] = y + ci + cj[2 * p + 1];
            }
            float4* dst = (float4*)(adj + (size_t)gr * n + gcb);
            float4 v0 = make_float4(o[0], o[1], o[2], o[3]);
            float4 v1 = make_float4(o[4], o[5], o[6], o[7]);
            __stcs(dst, v0);
            __stcs(dst + 1, v1);
        }
    }
}

// ---------------- launcher -----------------------------------------------------
extern "C" void kernel_launch(void* const* d_in, const int* in_sizes, int n_in,
                              void* d_out, int out_size) {
    const float* x       = (const float*)d_in[0];
    const void*  ei      = d_in[1];
    const float* enc_W1  = (const float*)d_in[2];
    const float* enc_b1  = (const float*)d_in[3];
    const float* enc_W2  = (const float*)d_in[4];
    const float* enc_b2  = (const float*)d_in[5];
    const float* attr_W1 = (const float*)d_in[6];
    const float* attr_b1 = (const float*)d_in[7];
    const float* attr_W2 = (const float*)d_in[8];
    const float* attr_b2 = (const float*)d_in[9];
    const float* Ws      = (const float*)d_in[10];
    const float* bs      = (const float*)d_in[11];
    float* out = (float*)d_out;

    int E = in_sizes[1] / 2;

    void* sp = nullptr;
    cudaGetSymbolAddress(&sp, d_scratch);
    float* scr = (float*)sp;
    float* B0 = scr + OFF_B0;   float* H1 = scr + OFF_H1;
    float* Q  = scr + OFF_Q;    float* H  = scr + OFF_H;
    float* R  = scr + OFF_R;    float* X1 = scr + OFF_X1;
    float* S  = scr + OFF_S;    float* P  = scr + OFF_P;
    float2* EP = (float2*)(scr + OFF_EPACK);
    float* G  = scr + OFF_G;    float* V  = scr + OFF_V;
    float* BB = scr + OFF_BB;   float* C  = scr + OFF_C;
    float* DINV = scr + OFF_DINV;
    float* SELFC = scr + OFF_SELFC;
    int* OFFS = (int*)(scr + OFF_OFFS);
    int* CUR  = (int*)(scr + OFF_CUR);
    int* CNT  = (int*)(scr + OFF_CNT);
    int* FLAG = (int*)(scr + OFF_FLAG);

    cudaFuncSetAttribute(k_adj, cudaFuncAttributeMaxDynamicSharedMemorySize, 65536);

    // graph build
    k_detect<<<1, 256>>>(ei, FLAG);
    k_zero<<<(NN + 255) / 256, 256>>>(CNT, NN);
    k_hist<<<(E + 255) / 256, 256>>>(ei, E, FLAG, CNT);
    k_scan<<<1, 1024>>>(CNT, OFFS, CUR, DINV, SELFC, NN);
    k_scatter<<<(E + 255) / 256, 256>>>(ei, E, FLAG, DINV, CUR, EP);

    dim3 gemm_grid1(1, 157), gemm_grid4(4, 157);
    int prop_blocks = (NN * 32 + 255) / 256;

    // encoder
    k_gemm<<<gemm_grid1, 256>>>(x, enc_W1, nullptr, B0, NN, 64, 256, 0);
    k_prop<<<prop_blocks, 256>>>(B0, H1, EP, OFFS, SELFC, enc_b1, 1, NN);
    k_prop<<<prop_blocks, 256>>>(H1, Q, EP, OFFS, SELFC, nullptr, 0, NN);
    k_gemm<<<gemm_grid1, 256>>>(Q, enc_W2, enc_b2, H, NN, 64, 64, 0);
    k_prop<<<prop_blocks, 256>>>(H, R, EP, OFFS, SELFC, nullptr, 0, NN);

    // attribute decoder
    k_gemm<<<gemm_grid1, 256>>>(R, attr_W1, attr_b1, X1, NN, 64, 64, 1);
    k_prop<<<prop_blocks, 256>>>(X1, S, EP, OFFS, SELFC, nullptr, 0, NN);
    k_gemm<<<gemm_grid4, 256>>>(S, attr_W2, attr_b2, out, NN, 256, 64, 0);

    // structure decoder via Gram factorization
    k_gram<<<16, 256>>>(Ws, bs, G, V, BB);
    k_gemm<<<gemm_grid1, 256>>>(R, G, nullptr, P, NN, 64, 64, 0);
    k_c<<<prop_blocks, 256>>>(R, V, BB, C, NN);

    dim3 adj_grid(79, 79);
    k_adj<<<adj_grid, 256, 65536>>>(P, R, C, out + (size_t)NN * INDIM, NN);
}

// round 4
// speedup vs baseline: 1.4448x; 1.4448x over previous
#include <cuda_runtime.h>
#include <cuda_bf16.h>
#include <cstddef>
#include <cstdint>

#define NN    10000
#define INDIM 256
#define HID   64

// ---------------- static scratch (no allocations allowed) --------------------
__device__ __align__(256) float d_scratch[5900000];

#define OFF_B0    0        // [NN,64] x@W1        (later reused: RHI/RLO bf16)
#define OFF_H1    640000   // relu(A@B0+b1)       (later reused: PHI/PLO bf16)
#define OFF_Q     1280000
#define OFF_H     1920000
#define OFF_R     2560000
#define OFF_X1    3200000
#define OFF_S     3840000
#define OFF_P     4480000
#define OFF_EPACK 5120000  // float2[320000] {src_bits, norm}
#define OFF_G     5760000
#define OFF_V     5764096
#define OFF_BB    5764160
#define OFF_C     5764224
#define OFF_DINV  5774224
#define OFF_SELFC 5784224
#define OFF_OFFS  5794224
#define OFF_CUR   5804240
#define OFF_CNT   5814240
#define OFF_FLAG  5824240

#define SWZ128(off) ((off) ^ (((off) >> 3) & 0x70))

__device__ __forceinline__ uint32_t smem_u32(const void* p) {
    uint32_t a;
    asm("{ .reg .u64 t; cvta.to.shared.u64 t, %1; cvt.u32.u64 %0, t; }" : "=r"(a) : "l"(p));
    return a;
}
__device__ __forceinline__ void ldsm4(uint32_t* r, uint32_t addr) {
    asm volatile("ldmatrix.sync.aligned.m8n8.x4.shared.b16 {%0,%1,%2,%3}, [%4];"
                 : "=r"(r[0]), "=r"(r[1]), "=r"(r[2]), "=r"(r[3]) : "r"(addr));
}
__device__ __forceinline__ void mma_bf16(float* d, const uint32_t* a, const uint32_t* b) {
    asm volatile(
        "mma.sync.aligned.m16n8k16.row.col.f32.bf16.bf16.f32 "
        "{%0,%1,%2,%3}, {%4,%5,%6,%7}, {%8,%9}, {%0,%1,%2,%3};"
        : "+f"(d[0]), "+f"(d[1]), "+f"(d[2]), "+f"(d[3])
        : "r"(a[0]), "r"(a[1]), "r"(a[2]), "r"(a[3]), "r"(b[0]), "r"(b[1]));
}

// ---------------- graph build --------------------------------------------------
__global__ void k_detect(const void* ei, int* flag) {
    __shared__ int cnt;
    if (threadIdx.x == 0) cnt = 0;
    __syncthreads();
    long long v = ((const long long*)ei)[threadIdx.x];
    if (v >= 0 && v < NN) atomicAdd(&cnt, 1);
    __syncthreads();
    if (threadIdx.x == 0) *flag = (cnt > 128) ? 1 : 0;
}

__global__ void k_zero(int* cnt, int n) {
    int i = blockIdx.x * blockDim.x + threadIdx.x;
    if (i < n) cnt[i] = 0;
}

__global__ void k_hist(const void* ei, int E, const int* __restrict__ flag,
                       int* __restrict__ cnt) {
    int e = blockIdx.x * blockDim.x + threadIdx.x;
    if (e >= E) return;
    int s, d;
    if (*flag) {
        const long long* p = (const long long*)ei;
        s = (int)p[e]; d = (int)p[E + e];
    } else {
        const int* p = (const int*)ei;
        s = p[e]; d = p[E + e];
    }
    if (s != d) atomicAdd(&cnt[d], 1);
}

__global__ void k_dinv(const int* __restrict__ cnt, float* __restrict__ dinv,
                       float* __restrict__ selfc, int n) {
    int i = blockIdx.x * blockDim.x + threadIdx.x;
    if (i < n) {
        float dg = (float)(cnt[i] + 1);
        dinv[i] = rsqrtf(dg);
        selfc[i] = 1.0f / dg;
    }
}

__global__ void k_scan(const int* __restrict__ cnt, int* __restrict__ offs,
                       int* __restrict__ cur, int n) {
    const int IT = 10;
    __shared__ int wsum[32];
    int tid = threadIdx.x;
    int base = tid * IT;
    int loc[IT];
    int s = 0;
#pragma unroll
    for (int k = 0; k < IT; k++) {
        int idx = base + k;
        int v = (idx < n) ? __ldg(&cnt[idx]) : 0;
        loc[k] = s;
        s += v;
    }
    int lane = tid & 31, wid = tid >> 5;
    int x = s;
#pragma unroll
    for (int o = 1; o < 32; o <<= 1) {
        int y = __shfl_up_sync(0xffffffffu, x, o);
        if (lane >= o) x += y;
    }
    if (lane == 31) wsum[wid] = x;
    __syncthreads();
    if (wid == 0) {
        int y = wsum[lane];
#pragma unroll
        for (int o = 1; o < 32; o <<= 1) {
            int z = __shfl_up_sync(0xffffffffu, y, o);
            if (lane >= o) y += z;
        }
        wsum[lane] = y;
    }
    __syncthreads();
    int pre = x - s + (wid ? wsum[wid - 1] : 0);
#pragma unroll
    for (int k = 0; k < IT; k++) {
        int idx = base + k;
        if (idx < n) { offs[idx] = pre + loc[k]; cur[idx] = pre + loc[k]; }
        else if (idx == n) { offs[n] = pre + loc[k]; }
    }
}

__global__ void k_scatter(const void* ei, int E, const int* __restrict__ flag,
                          const float* __restrict__ dinv, int* __restrict__ cur,
                          float2* __restrict__ epack) {
    int e = blockIdx.x * blockDim.x + threadIdx.x;
    if (e >= E) return;
    int s, d;
    if (*flag) {
        const long long* p = (const long long*)ei;
        s = (int)p[e]; d = (int)p[E + e];
    } else {
        const int* p = (const int*)ei;
        s = p[e]; d = p[E + e];
    }
    if (s != d) {
        int pos = atomicAdd(&cur[d], 1);
        epack[pos] = make_float2(__int_as_float(s), dinv[s] * dinv[d]);
    }
}

// ---------------- GCN propagation: out = A_norm @ y (+bias)(+relu), dim=64 ----
__global__ void k_prop(const float* __restrict__ y, float* __restrict__ out,
                       const float2* __restrict__ ep, const int* __restrict__ offs,
                       const float* __restrict__ selfc, const float* __restrict__ bias,
                       int relu, int n) {
    int w = (blockIdx.x * blockDim.x + threadIdx.x) >> 5;
    int lane = threadIdx.x & 31;
    if (w >= n) return;
    const float2* Y = (const float2*)y;
    float sc = selfc[w];
    float2 yd = Y[w * 32 + lane];
    float ax = sc * yd.x, ay = sc * yd.y;
    int e = offs[w], e1 = offs[w + 1];
    for (; e + 1 < e1; e += 2) {
        float2 p0 = ep[e], p1 = ep[e + 1];
        float2 y0 = Y[__float_as_int(p0.x) * 32 + lane];
        float2 y1 = Y[__float_as_int(p1.x) * 32 + lane];
        ax = fmaf(p0.y, y0.x, ax); ay = fmaf(p0.y, y0.y, ay);
        ax = fmaf(p1.y, y1.x, ax); ay = fmaf(p1.y, y1.y, ay);
    }
    if (e < e1) {
        float2 p0 = ep[e];
        float2 y0 = Y[__float_as_int(p0.x) * 32 + lane];
        ax = fmaf(p0.y, y0.x, ax); ay = fmaf(p0.y, y0.y, ay);
    }
    if (bias) {
        float2 b = ((const float2*)bias)[lane];
        ax += b.x; ay += b.y;
    }
    if (relu) { ax = fmaxf(ax, 0.f); ay = fmaxf(ay, 0.f); }
    ((float2*)out)[w * 32 + lane] = make_float2(ax, ay);
}

// ---------------- small GEMM: C[M,N] = A[M,K] @ W[K,N] (+bias)(+relu) ----------
__global__ __launch_bounds__(256) void k_gemm(
    const float* __restrict__ A, const float* __restrict__ W,
    const float* __restrict__ bias, float* __restrict__ C,
    int M, int N, int K, int relu) {
    __shared__ float As[16][68];
    __shared__ float Ws[16][68];
    int tid = threadIdx.x;
    int row0 = blockIdx.y * 64, col0 = blockIdx.x * 64;
    int tx = tid & 15, ty = tid >> 4;
    int lr = tid >> 2, lq = tid & 3;
    int wr = tid >> 4, wc = tid & 15;
    float acc[4][4];
#pragma unroll
    for (int i = 0; i < 4; i++)
#pragma unroll
        for (int j = 0; j < 4; j++) acc[i][j] = 0.f;

    for (int k0 = 0; k0 < K; k0 += 16) {
        int ar = min(row0 + lr, M - 1);
        float4 av = *(const float4*)&A[(size_t)ar * K + k0 + 4 * lq];
        As[4 * lq + 0][lr] = av.x; As[4 * lq + 1][lr] = av.y;
        As[4 * lq + 2][lr] = av.z; As[4 * lq + 3][lr] = av.w;
        float4 wv = *(const float4*)&W[(size_t)(k0 + wr) * N + col0 + 4 * wc];
        *(float4*)&Ws[wr][4 * wc] = wv;
        __syncthreads();
#pragma unroll
        for (int k = 0; k < 16; k++) {
            float4 a = *(float4*)&As[k][ty * 4];
            float4 b = *(float4*)&Ws[k][tx * 4];
            acc[0][0] = fmaf(a.x, b.x, acc[0][0]); acc[0][1] = fmaf(a.x, b.y, acc[0][1]);
            acc[0][2] = fmaf(a.x, b.z, acc[0][2]); acc[0][3] = fmaf(a.x, b.w, acc[0][3]);
            acc[1][0] = fmaf(a.y, b.x, acc[1][0]); acc[1][1] = fmaf(a.y, b.y, acc[1][1]);
            acc[1][2] = fmaf(a.y, b.z, acc[1][2]); acc[1][3] = fmaf(a.y, b.w, acc[1][3]);
            acc[2][0] = fmaf(a.z, b.x, acc[2][0]); acc[2][1] = fmaf(a.z, b.y, acc[2][1]);
            acc[2][2] = fmaf(a.z, b.z, acc[2][2]); acc[2][3] = fmaf(a.z, b.w, acc[2][3]);
            acc[3][0] = fmaf(a.w, b.x, acc[3][0]); acc[3][1] = fmaf(a.w, b.y, acc[3][1]);
            acc[3][2] = fmaf(a.w, b.z, acc[3][2]); acc[3][3] = fmaf(a.w, b.w, acc[3][3]);
        }
        __syncthreads();
    }
    float4 bv = make_float4(0.f, 0.f, 0.f, 0.f);
    if (bias) bv = *(const float4*)&bias[col0 + tx * 4];
#pragma unroll
    for (int i = 0; i < 4; i++) {
        int gr = row0 + ty * 4 + i;
        if (gr < M) {
            float4 o;
            o.x = acc[i][0] + bv.x; o.y = acc[i][1] + bv.y;
            o.z = acc[i][2] + bv.z; o.w = acc[i][3] + bv.w;
            if (relu) {
                o.x = fmaxf(o.x, 0.f); o.y = fmaxf(o.y, 0.f);
                o.z = fmaxf(o.z, 0.f); o.w = fmaxf(o.w, 0.f);
            }
            *(float4*)&C[(size_t)gr * N + col0 + tx * 4] = o;
        }
    }
}

// ---------------- G = Ws Ws^T, v = Ws bs, bb = bs.bs ---------------------------
__global__ void k_gram(const float* __restrict__ Ws, const float* __restrict__ bs,
                       float* __restrict__ G, float* __restrict__ v, float* __restrict__ bb) {
    int idx = blockIdx.x * blockDim.x + threadIdx.x;
    if (idx < 4096) {
        int i = idx >> 6, j = idx & 63;
        const float4* a = (const float4*)(Ws + i * 256);
        const float4* b = (const float4*)(Ws + j * 256);
        float s = 0.f;
#pragma unroll 8
        for (int k = 0; k < 64; k++) {
            float4 x = __ldg(&a[k]), y = __ldg(&b[k]);
            s += x.x * y.x + x.y * y.y + x.z * y.z + x.w * y.w;
        }
        G[idx] = s;
        if (j == 0) {
            const float4* c = (const float4*)bs;
            float t = 0.f;
#pragma unroll 8
            for (int k = 0; k < 64; k++) {
                float4 x = __ldg(&a[k]), y = __ldg(&c[k]);
                t += x.x * y.x + x.y * y.y + x.z * y.z + x.w * y.w;
            }
            v[i] = t;
        }
        if (idx == 0) {
            const float4* c = (const float4*)bs;
            float t = 0.f;
#pragma unroll 8
            for (int k = 0; k < 64; k++) {
                float4 y = __ldg(&c[k]);
                t += y.x * y.x + y.y * y.y + y.z * y.z + y.w * y.w;
            }
            bb[0] = t;
        }
    }
}

// ---------------- c'[i] = R[i].v + bb/2 ---------------------------------------
__global__ void k_c(const float* __restrict__ R, const float* __restrict__ v,
                    const float* __restrict__ bb, float* __restrict__ c, int n) {
    int w = (blockIdx.x * blockDim.x + threadIdx.x) >> 5;
    int lane = threadIdx.x & 31;
    if (w >= n) return;
    float2 r2 = ((const float2*)R)[w * 32 + lane];
    float2 v2 = ((const float2*)v)[lane];
    float s = r2.x * v2.x + r2.y * v2.y;
#pragma unroll
    for (int o = 16; o; o >>= 1) s += __shfl_xor_sync(0xffffffffu, s, o);
    if (lane == 0) c[w] = s + 0.5f * bb[0];
}

// ---------------- split fp32 -> bf16 hi + bf16 lo residual ---------------------
__global__ void k_split(const float* __restrict__ X, __nv_bfloat16* __restrict__ hi,
                        __nv_bfloat16* __restrict__ lo, int nelem) {
    int i = blockIdx.x * blockDim.x + threadIdx.x;
    if (i < nelem) {
        float v = X[i];
        __nv_bfloat16 h = __float2bfloat16(v);
        float r = v - __bfloat162float(h);
        hi[i] = h;
        lo[i] = __float2bfloat16(r);
    }
}

// ---------------- adj 128x128 tile via HMMA bf16-split --------------------------
// D = Phi@Rhi^T + Phi@Rlo^T + Plo@Rhi^T (fp32 accum), epilogue + ci + cj
#define SMA_PHI 0
#define SMA_PLO 16384
#define SMA_RHI 32768
#define SMA_RLO 49152
#define SMA_CJ  65536
#define SMA_TOTAL (65536 + 512)

__global__ __launch_bounds__(256, 1) void k_adj(
    const __nv_bfloat16* __restrict__ Phi, const __nv_bfloat16* __restrict__ Plo,
    const __nv_bfloat16* __restrict__ Rhi, const __nv_bfloat16* __restrict__ Rlo,
    const float* __restrict__ c, float* __restrict__ adj, int n) {
    extern __shared__ char smem[];
    uint32_t sb = smem_u32(smem);
    int tid = threadIdx.x, wid = tid >> 5, lane = tid & 31;
    int row0 = blockIdx.y * 128, col0 = blockIdx.x * 128;

    // G2S: 128 rows x 128B per tile, SW128-swizzled. 256 thr x 16B = 8 rows/pass.
    {
        const float4* gphi = (const float4*)Phi;
        const float4* gplo = (const float4*)Plo;
        const float4* grhi = (const float4*)Rhi;
        const float4* grlo = (const float4*)Rlo;
#pragma unroll
        for (int it = 0; it < 4; it++) {
            int idx = it * 256 + tid;
            int r = idx >> 3, ch = idx & 7;
            uint32_t so = SWZ128((uint32_t)(r * 128 + ch * 16));
            size_t prow = (size_t)min(row0 + r, n - 1) * 8 + ch;
            size_t rrow = (size_t)min(col0 + r, n - 1) * 8 + ch;
            *(float4*)(smem + SMA_PHI + so) = __ldg(&gphi[prow]);
            *(float4*)(smem + SMA_PLO + so) = __ldg(&gplo[prow]);
            *(float4*)(smem + SMA_RHI + so) = __ldg(&grhi[rrow]);
            *(float4*)(smem + SMA_RLO + so) = __ldg(&grlo[rrow]);
        }
        if (tid < 128)
            ((float*)(smem + SMA_CJ))[tid] = __ldg(&c[min(col0 + tid, n - 1)]);
    }
    __syncthreads();

    int wm = wid >> 2, wn = wid & 3;  // 2x4 warp grid, warp tile 64x32
    float acc[4][4][4];
#pragma unroll
    for (int i = 0; i < 4; i++)
#pragma unroll
        for (int j = 0; j < 4; j++)
#pragma unroll
            for (int q = 0; q < 4; q++) acc[i][j][q] = 0.f;

    // ldmatrix lane address components
    int a_row = wm * 64 + ((lane >> 3) & 1) * 8 + (lane & 7);
    int a_kb  = (lane >> 4) * 16;
    int b_row = wn * 32 + (lane >> 4) * 8 + (lane & 7);
    int b_kb  = ((lane >> 3) & 1) * 16;

#pragma unroll
    for (int k = 0; k < 4; k++) {
        int kb = k * 32;  // 16 bf16 = 32 bytes per k-step
        uint32_t af[4][4], bh[8], bl[8];
#pragma unroll
        for (int i = 0; i < 4; i++)
            ldsm4(af[i], sb + SMA_PHI + SWZ128((uint32_t)((a_row + i * 16) * 128 + a_kb + kb)));
        ldsm4(bh,     sb + SMA_RHI + SWZ128((uint32_t)(b_row * 128 + b_kb + kb)));
        ldsm4(bh + 4, sb + SMA_RHI + SWZ128((uint32_t)((b_row + 16) * 128 + b_kb + kb)));
        ldsm4(bl,     sb + SMA_RLO + SWZ128((uint32_t)(b_row * 128 + b_kb + kb)));
        ldsm4(bl + 4, sb + SMA_RLO + SWZ128((uint32_t)((b_row + 16) * 128 + b_kb + kb)));
#pragma unroll
        for (int i = 0; i < 4; i++)
#pragma unroll
            for (int j = 0; j < 4; j++) {
                mma_bf16(acc[i][j], af[i], &bh[j * 2]);
                mma_bf16(acc[i][j], af[i], &bl[j * 2]);
            }
        // reuse af for Plo fragments
#pragma unroll
        for (int i = 0; i < 4; i++)
            ldsm4(af[i], sb + SMA_PLO + SWZ128((uint32_t)((a_row + i * 16) * 128 + a_kb + kb)));
#pragma unroll
        for (int i = 0; i < 4; i++)
#pragma unroll
            for (int j = 0; j < 4; j++)
                mma_bf16(acc[i][j], af[i], &bh[j * 2]);
    }

    // epilogue: + ci + cj, streamed stores
    const float* cjs = (const float*)(smem + SMA_CJ);
    int rbase = row0 + wm * 64 + (lane >> 2);
    int cbase = wn * 32 + (lane & 3) * 2;
#pragma unroll
    for (int i = 0; i < 4; i++) {
#pragma unroll
        for (int h = 0; h < 2; h++) {
            int grow = rbase + i * 16 + h * 8;
            if (grow < n) {
                float ci = __ldg(&c[grow]);
                float* dst = adj + (size_t)grow * n;
#pragma unroll
                for (int j = 0; j < 4; j++) {
                    int lcol = cbase + j * 8;
                    int gcol = col0 + lcol;
                    if (gcol < n) {  // n even, gcol even -> gcol+1 < n too
                        float2 o;
                        o.x = acc[i][j][h * 2 + 0] + ci + cjs[lcol];
                        o.y = acc[i][j][h * 2 + 1] + ci + cjs[lcol + 1];
                        __stcs((float2*)(dst + gcol), o);
                    }
                }
            }
        }
    }
}

// ---------------- launcher -----------------------------------------------------
extern "C" void kernel_launch(void* const* d_in, const int* in_sizes, int n_in,
                              void* d_out, int out_size) {
    const float* x       = (const float*)d_in[0];
    const void*  ei      = d_in[1];
    const float* enc_W1  = (const float*)d_in[2];
    const float* enc_b1  = (const float*)d_in[3];
    const float* enc_W2  = (const float*)d_in[4];
    const float* enc_b2  = (const float*)d_in[5];
    const float* attr_W1 = (const float*)d_in[6];
    const float* attr_b1 = (const float*)d_in[7];
    const float* attr_W2 = (const float*)d_in[8];
    const float* attr_b2 = (const float*)d_in[9];
    const float* Ws      = (const float*)d_in[10];
    const float* bs      = (const float*)d_in[11];
    float* out = (float*)d_out;

    int E = in_sizes[1] / 2;

    void* sp = nullptr;
    cudaGetSymbolAddress(&sp, d_scratch);
    float* scr = (float*)sp;
    float* B0 = scr + OFF_B0;   float* H1 = scr + OFF_H1;
    float* Q  = scr + OFF_Q;    float* H  = scr + OFF_H;
    float* R  = scr + OFF_R;    float* X1 = scr + OFF_X1;
    float* S  = scr + OFF_S;    float* P  = scr + OFF_P;
    float2* EP = (float2*)(scr + OFF_EPACK);
    float* G  = scr + OFF_G;    float* V  = scr + OFF_V;
    float* BB = scr + OFF_BB;   float* C  = scr + OFF_C;
    float* DINV = scr + OFF_DINV;
    float* SELFC = scr + OFF_SELFC;
    int* OFFS = (int*)(scr + OFF_OFFS);
    int* CUR  = (int*)(scr + OFF_CUR);
    int* CNT  = (int*)(scr + OFF_CNT);
    int* FLAG = (int*)(scr + OFF_FLAG);

    // bf16 split buffers reuse dead fp32 scratch (B0/H1 dead by then)
    __nv_bfloat16* RHI = (__nv_bfloat16*)(scr + OFF_B0);
    __nv_bfloat16* RLO = (__nv_bfloat16*)(scr + OFF_B0 + 320000);
    __nv_bfloat16* PHI = (__nv_bfloat16*)(scr + OFF_H1);
    __nv_bfloat16* PLO = (__nv_bfloat16*)(scr + OFF_H1 + 320000);

    cudaFuncSetAttribute(k_adj, cudaFuncAttributeMaxDynamicSharedMemorySize, SMA_TOTAL);

    // graph build
    k_detect<<<1, 256>>>(ei, FLAG);
    k_zero<<<(NN + 255) / 256, 256>>>(CNT, NN);
    k_hist<<<(E + 255) / 256, 256>>>(ei, E, FLAG, CNT);
    k_dinv<<<(NN + 255) / 256, 256>>>(CNT, DINV, SELFC, NN);
    k_scan<<<1, 1024>>>(CNT, OFFS, CUR, NN);
    k_scatter<<<(E + 255) / 256, 256>>>(ei, E, FLAG, DINV, CUR, EP);

    dim3 gemm_grid1(1, 157), gemm_grid4(4, 157);
    int prop_blocks = (NN * 32 + 255) / 256;

    // encoder
    k_gemm<<<gemm_grid1, 256>>>(x, enc_W1, nullptr, B0, NN, 64, 256, 0);
    k_prop<<<prop_blocks, 256>>>(B0, H1, EP, OFFS, SELFC, enc_b1, 1, NN);
    k_prop<<<prop_blocks, 256>>>(H1, Q, EP, OFFS, SELFC, nullptr, 0, NN);
    k_gemm<<<gemm_grid1, 256>>>(Q, enc_W2, enc_b2, H, NN, 64, 64, 0);
    k_prop<<<prop_blocks, 256>>>(H, R, EP, OFFS, SELFC, nullptr, 0, NN);

    // attribute decoder
    k_gemm<<<gemm_grid1, 256>>>(R, attr_W1, attr_b1, X1, NN, 64, 64, 1);
    k_prop<<<prop_blocks, 256>>>(X1, S, EP, OFFS, SELFC, nullptr, 0, NN);
    k_gemm<<<gemm_grid4, 256>>>(S, attr_W2, attr_b2, out, NN, 256, 64, 0);

    // structure decoder via Gram factorization
    k_gram<<<16, 256>>>(Ws, bs, G, V, BB);
    k_gemm<<<gemm_grid1, 256>>>(R, G, nullptr, P, NN, 64, 64, 0);
    k_c<<<prop_blocks, 256>>>(R, V, BB, C, NN);

    // split to bf16 hi/lo
    k_split<<<(NN * 64 + 255) / 256, 256>>>(R, RHI, RLO, NN * 64);
    k_split<<<(NN * 64 + 255) / 256, 256>>>(P, PHI, PLO, NN * 64);

    // adj = P @ R^T + c_i + c_j  (HMMA bf16-split)
    dim3 adj_grid((NN + 127) / 128, (NN + 127) / 128);
    k_adj<<<adj_grid, 256, SMA_TOTAL>>>(PHI, PLO, RHI, RLO, C,
                                        out + (size_t)NN * INDIM, NN);
}

// round 6
// speedup vs baseline: 2.0092x; 1.3907x over previous
#include <cuda_runtime.h>
#include <cuda_bf16.h>
#include <cstddef>
#include <cstdint>

#define NN    10000
#define INDIM 256
#define HID   64

// ---------------- static scratch (no allocations allowed) --------------------
__device__ __align__(256) float d_scratch[5900000];

#define OFF_B0    0
#define OFF_H1    640000
#define OFF_Q     1280000
#define OFF_H     1920000
#define OFF_R     2560000
#define OFF_X1    3200000
#define OFF_S     3840000
#define OFF_P     4480000
#define OFF_EPACK 5120000
#define OFF_G     5760000
#define OFF_V     5764096
#define OFF_BB    5764160
#define OFF_C     5764224
#define OFF_DINV  5774224
#define OFF_SELFC 5784224
#define OFF_OFFS  5794224
#define OFF_CUR   5804240
#define OFF_CNT   5814240
#define OFF_FLAG  5824240

#define SWZ128(off) ((off) ^ (((off) >> 3) & 0x70))

__device__ __forceinline__ uint32_t smem_u32(const void* p) {
    uint32_t a;
    asm("{ .reg .u64 t; cvta.to.shared.u64 t, %1; cvt.u32.u64 %0, t; }" : "=r"(a) : "l"(p));
    return a;
}
__device__ __forceinline__ void ldsm4(uint32_t* r, uint32_t addr) {
    asm volatile("ldmatrix.sync.aligned.m8n8.x4.shared.b16 {%0,%1,%2,%3}, [%4];"
                 : "=r"(r[0]), "=r"(r[1]), "=r"(r[2]), "=r"(r[3]) : "r"(addr));
}
__device__ __forceinline__ void mma_bf16(float* d, const uint32_t* a, const uint32_t* b) {
    asm volatile(
        "mma.sync.aligned.m16n8k16.row.col.f32.bf16.bf16.f32 "
        "{%0,%1,%2,%3}, {%4,%5,%6,%7}, {%8,%9}, {%0,%1,%2,%3};"
        : "+f"(d[0]), "+f"(d[1]), "+f"(d[2]), "+f"(d[3])
        : "r"(a[0]), "r"(a[1]), "r"(a[2]), "r"(a[3]), "r"(b[0]), "r"(b[1]));
}

// ---------------- graph build: zero counts + dtype detect ----------------------
__global__ void k_init(const void* ei, int* cnt, int* flag, int n) {
    int i = blockIdx.x * blockDim.x + threadIdx.x;
    if (i < n) cnt[i] = 0;
    if (blockIdx.x == 0) {
        __shared__ int c;
        if (threadIdx.x == 0) c = 0;
        __syncthreads();
        long long v = ((const long long*)ei)[threadIdx.x];
        if (v >= 0 && v < NN) atomicAdd(&c, 1);
        __syncthreads();
        if (threadIdx.x == 0) *flag = (c > 128) ? 1 : 0;
    }
}

__global__ void k_hist(const void* ei, int E, const int* __restrict__ flag,
                       int* __restrict__ cnt) {
    int e = blockIdx.x * blockDim.x + threadIdx.x;
    if (e >= E) return;
    int s, d;
    if (*flag) {
        const long long* p = (const long long*)ei;
        s = (int)p[e]; d = (int)p[E + e];
    } else {
        const int* p = (const int*)ei;
        s = p[e]; d = p[E + e];
    }
    if (s != d) atomicAdd(&cnt[d], 1);
}

// scan of counts -> offsets/cursors, plus dinv/selfc
__global__ void k_scan(const int* __restrict__ cnt, int* __restrict__ offs,
                       int* __restrict__ cur, float* __restrict__ dinv,
                       float* __restrict__ selfc, int n) {
    const int IT = 10;
    __shared__ int wsum[32];
    int tid = threadIdx.x;
    int base = tid * IT;
    int loc[IT];
    int s = 0;
#pragma unroll
    for (int k = 0; k < IT; k++) {
        int idx = base + k;
        int v = (idx < n) ? __ldg(&cnt[idx]) : 0;
        loc[k] = s;
        s += v;
        if (idx < n) {
            float dg = (float)(v + 1);
            dinv[idx] = rsqrtf(dg);
            selfc[idx] = 1.0f / dg;
        }
    }
    int lane = tid & 31, wid = tid >> 5;
    int x = s;
#pragma unroll
    for (int o = 1; o < 32; o <<= 1) {
        int y = __shfl_up_sync(0xffffffffu, x, o);
        if (lane >= o) x += y;
    }
    if (lane == 31) wsum[wid] = x;
    __syncthreads();
    if (wid == 0) {
        int y = wsum[lane];
#pragma unroll
        for (int o = 1; o < 32; o <<= 1) {
            int z = __shfl_up_sync(0xffffffffu, y, o);
            if (lane >= o) y += z;
        }
        wsum[lane] = y;
    }
    __syncthreads();
    int pre = x - s + (wid ? wsum[wid - 1] : 0);
#pragma unroll
    for (int k = 0; k < IT; k++) {
        int idx = base + k;
        if (idx < n) { offs[idx] = pre + loc[k]; cur[idx] = pre + loc[k]; }
        else if (idx == n) { offs[n] = pre + loc[k]; }
    }
}

__global__ void k_scatter(const void* ei, int E, const int* __restrict__ flag,
                          const float* __restrict__ dinv, int* __restrict__ cur,
                          float2* __restrict__ epack) {
    int e = blockIdx.x * blockDim.x + threadIdx.x;
    if (e >= E) return;
    int s, d;
    if (*flag) {
        const long long* p = (const long long*)ei;
        s = (int)p[e]; d = (int)p[E + e];
    } else {
        const int* p = (const int*)ei;
        s = p[e]; d = p[E + e];
    }
    if (s != d) {
        int pos = atomicAdd(&cur[d], 1);
        epack[pos] = make_float2(__int_as_float(s), dinv[s] * dinv[d]);
    }
}

// ---------------- GCN propagation: out = A_norm @ y (+bias)(+relu), dim=64 ----
__global__ void k_prop(const float* __restrict__ y, float* __restrict__ out,
                       const float2* __restrict__ ep, const int* __restrict__ offs,
                       const float* __restrict__ selfc, const float* __restrict__ bias,
                       int relu, int n) {
    int w = (blockIdx.x * blockDim.x + threadIdx.x) >> 5;
    int lane = threadIdx.x & 31;
    if (w >= n) return;
    const float2* Y = (const float2*)y;
    float sc = selfc[w];
    float2 yd = Y[w * 32 + lane];
    float ax = sc * yd.x, ay = sc * yd.y;
    int e = offs[w], e1 = offs[w + 1];
    for (; e + 1 < e1; e += 2) {
        float2 p0 = ep[e], p1 = ep[e + 1];
        float2 y0 = Y[__float_as_int(p0.x) * 32 + lane];
        float2 y1 = Y[__float_as_int(p1.x) * 32 + lane];
        ax = fmaf(p0.y, y0.x, ax); ay = fmaf(p0.y, y0.y, ay);
        ax = fmaf(p1.y, y1.x, ax); ay = fmaf(p1.y, y1.y, ay);
    }
    if (e < e1) {
        float2 p0 = ep[e];
        float2 y0 = Y[__float_as_int(p0.x) * 32 + lane];
        ax = fmaf(p0.y, y0.x, ax); ay = fmaf(p0.y, y0.y, ay);
    }
    if (bias) {
        float2 b = ((const float2*)bias)[lane];
        ax += b.x; ay += b.y;
    }
    if (relu) { ax = fmaxf(ax, 0.f); ay = fmaxf(ay, 0.f); }
    ((float2*)out)[w * 32 + lane] = make_float2(ax, ay);
}

// ---------------- small GEMM: C[M,N] = A[M,K] @ W[K,N] (+bias)(+relu) ----------
__global__ __launch_bounds__(256) void k_gemm(
    const float* __restrict__ A, const float* __restrict__ W,
    const float* __restrict__ bias, float* __restrict__ C,
    int M, int N, int K, int relu) {
    __shared__ float As[16][68];
    __shared__ float Ws[16][68];
    int tid = threadIdx.x;
    int row0 = blockIdx.y * 64, col0 = blockIdx.x * 64;
    int tx = tid & 15, ty = tid >> 4;
    int lr = tid >> 2, lq = tid & 3;
    int wr = tid >> 4, wc = tid & 15;
    float acc[4][4];
#pragma unroll
    for (int i = 0; i < 4; i++)
#pragma unroll
        for (int j = 0; j < 4; j++) acc[i][j] = 0.f;

    for (int k0 = 0; k0 < K; k0 += 16) {
        int ar = min(row0 + lr, M - 1);
        float4 av = *(const float4*)&A[(size_t)ar * K + k0 + 4 * lq];
        As[4 * lq + 0][lr] = av.x; As[4 * lq + 1][lr] = av.y;
        As[4 * lq + 2][lr] = av.z; As[4 * lq + 3][lr] = av.w;
        float4 wv = *(const float4*)&W[(size_t)(k0 + wr) * N + col0 + 4 * wc];
        *(float4*)&Ws[wr][4 * wc] = wv;
        __syncthreads();
#pragma unroll
        for (int k = 0; k < 16; k++) {
            float4 a = *(float4*)&As[k][ty * 4];
            float4 b = *(float4*)&Ws[k][tx * 4];
            acc[0][0] = fmaf(a.x, b.x, acc[0][0]); acc[0][1] = fmaf(a.x, b.y, acc[0][1]);
            acc[0][2] = fmaf(a.x, b.z, acc[0][2]); acc[0][3] = fmaf(a.x, b.w, acc[0][3]);
            acc[1][0] = fmaf(a.y, b.x, acc[1][0]); acc[1][1] = fmaf(a.y, b.y, acc[1][1]);
            acc[1][2] = fmaf(a.y, b.z, acc[1][2]); acc[1][3] = fmaf(a.y, b.w, acc[1][3]);
            acc[2][0] = fmaf(a.z, b.x, acc[2][0]); acc[2][1] = fmaf(a.z, b.y, acc[2][1]);
            acc[2][2] = fmaf(a.z, b.z, acc[2][2]); acc[2][3] = fmaf(a.z, b.w, acc[2][3]);
            acc[3][0] = fmaf(a.w, b.x, acc[3][0]); acc[3][1] = fmaf(a.w, b.y, acc[3][1]);
            acc[3][2] = fmaf(a.w, b.z, acc[3][2]); acc[3][3] = fmaf(a.w, b.w, acc[3][3]);
        }
        __syncthreads();
    }
    float4 bv = make_float4(0.f, 0.f, 0.f, 0.f);
    if (bias) bv = *(const float4*)&bias[col0 + tx * 4];
#pragma unroll
    for (int i = 0; i < 4; i++) {
        int gr = row0 + ty * 4 + i;
        if (gr < M) {
            float4 o;
            o.x = acc[i][0] + bv.x; o.y = acc[i][1] + bv.y;
            o.z = acc[i][2] + bv.z; o.w = acc[i][3] + bv.w;
            if (relu) {
                o.x = fmaxf(o.x, 0.f); o.y = fmaxf(o.y, 0.f);
                o.z = fmaxf(o.z, 0.f); o.w = fmaxf(o.w, 0.f);
            }
            *(float4*)&C[(size_t)gr * N + col0 + tx * 4] = o;
        }
    }
}

// ---------------- G = Ws Ws^T, v = Ws bs, bb = bs.bs ---------------------------
__global__ void k_gram(const float* __restrict__ Ws, const float* __restrict__ bs,
                       float* __restrict__ G, float* __restrict__ v, float* __restrict__ bb) {
    int idx = blockIdx.x * blockDim.x + threadIdx.x;
    if (idx < 4096) {
        int i = idx >> 6, j = idx & 63;
        const float4* a = (const float4*)(Ws + i * 256);
        const float4* b = (const float4*)(Ws + j * 256);
        float s = 0.f;
#pragma unroll 8
        for (int k = 0; k < 64; k++) {
            float4 x = __ldg(&a[k]), y = __ldg(&b[k]);
            s += x.x * y.x + x.y * y.y + x.z * y.z + x.w * y.w;
        }
        G[idx] = s;
        if (j == 0) {
            const float4* c = (const float4*)bs;
            float t = 0.f;
#pragma unroll 8
            for (int k = 0; k < 64; k++) {
                float4 x = __ldg(&a[k]), y = __ldg(&c[k]);
                t += x.x * y.x + x.y * y.y + x.z * y.z + x.w * y.w;
            }
            v[i] = t;
        }
        if (idx == 0) {
            const float4* c = (const float4*)bs;
            float t = 0.f;
#pragma unroll 8
            for (int k = 0; k < 64; k++) {
                float4 y = __ldg(&c[k]);
                t += y.x * y.x + y.y * y.y + y.z * y.z + y.w * y.w;
            }
            bb[0] = t;
        }
    }
}

// ---------------- c'[i] = R[i].v + bb/2 ---------------------------------------
__global__ void k_c(const float* __restrict__ R, const float* __restrict__ v,
                    const float* __restrict__ bb, float* __restrict__ c, int n) {
    int w = (blockIdx.x * blockDim.x + threadIdx.x) >> 5;
    int lane = threadIdx.x & 31;
    if (w >= n) return;
    float2 r2 = ((const float2*)R)[w * 32 + lane];
    float2 v2 = ((const float2*)v)[lane];
    float s = r2.x * v2.x + r2.y * v2.y;
#pragma unroll
    for (int o = 16; o; o >>= 1) s += __shfl_xor_sync(0xffffffffu, s, o);
    if (lane == 0) c[w] = s + 0.5f * bb[0];
}

// ---------------- split fp32 -> bf16 hi + lo for BOTH R and P ------------------
__global__ void k_split2(const float* __restrict__ R, const float* __restrict__ P,
                         __nv_bfloat16* __restrict__ rhi, __nv_bfloat16* __restrict__ rlo,
                         __nv_bfloat16* __restrict__ phi, __nv_bfloat16* __restrict__ plo,
                         int nelem) {
    int i = blockIdx.x * blockDim.x + threadIdx.x;
    if (i < nelem) {
        float v = R[i];
        __nv_bfloat16 h = __float2bfloat16(v);
        rhi[i] = h;
        rlo[i] = __float2bfloat16(v - __bfloat162float(h));
    } else if (i < 2 * nelem) {
        int j = i - nelem;
        float v = P[j];
        __nv_bfloat16 h = __float2bfloat16(v);
        phi[j] = h;
        plo[j] = __float2bfloat16(v - __bfloat162float(h));
    }
}

// ---------------- adj lower-triangle 128x128 tile + mirror ---------------------
// D = Phi@Rhi^T + Phi@Rlo^T + Plo@Rhi^T (fp32), + ci + cj; symmetric output.
#define SMA_PHI 0
#define SMA_PLO 16384
#define SMA_RHI 32768
#define SMA_RLO 49152
#define SMA_CJ  65536
#define TPAD 132                       // transpose row pad: 132*4B = 528B, 16B-aligned rows
#define SMA_TOTAL (128 * TPAD * 4)     // 67584 >= 66048 operand area it reuses

__global__ __launch_bounds__(256) void k_adj(
    const __nv_bfloat16* __restrict__ Phi, const __nv_bfloat16* __restrict__ Plo,
    const __nv_bfloat16* __restrict__ Rhi, const __nv_bfloat16* __restrict__ Rlo,
    const float* __restrict__ c, float* __restrict__ adj, int n) {
    extern __shared__ char smem[];
    uint32_t sb = smem_u32(smem);
    int tid = threadIdx.x, wid = tid >> 5, lane = tid & 31;

    // triangular decode: t -> (bi >= bj)
    int t = blockIdx.x;
    int bi = (int)((sqrtf(8.0f * (float)t + 1.0f) - 1.0f) * 0.5f);
    while ((bi + 1) * (bi + 2) / 2 <= t) bi++;
    while (bi * (bi + 1) / 2 > t) bi--;
    int bj = t - bi * (bi + 1) / 2;
    int row0 = bi * 128, col0 = bj * 128;

    // G2S: 128 rows x 128B per tile, SW128-swizzled
    {
        const float4* gphi = (const float4*)Phi;
        const float4* gplo = (const float4*)Plo;
        const float4* grhi = (const float4*)Rhi;
        const float4* grlo = (const float4*)Rlo;
#pragma unroll
        for (int it = 0; it < 4; it++) {
            int idx = it * 256 + tid;
            int r = idx >> 3, ch = idx & 7;
            uint32_t so = SWZ128((uint32_t)(r * 128 + ch * 16));
            size_t prow = (size_t)min(row0 + r, n - 1) * 8 + ch;
            size_t rrow = (size_t)min(col0 + r, n - 1) * 8 + ch;
            *(float4*)(smem + SMA_PHI + so) = __ldg(&gphi[prow]);
            *(float4*)(smem + SMA_PLO + so) = __ldg(&gplo[prow]);
            *(float4*)(smem + SMA_RHI + so) = __ldg(&grhi[rrow]);
            *(float4*)(smem + SMA_RLO + so) = __ldg(&grlo[rrow]);
        }
        if (tid < 128)
            ((float*)(smem + SMA_CJ))[tid] = __ldg(&c[min(col0 + tid, n - 1)]);
    }
    __syncthreads();

    int wm = wid >> 2, wn = wid & 3;  // 2x4 warp grid, warp tile 64x32
    float acc[4][4][4];
#pragma unroll
    for (int i = 0; i < 4; i++)
#pragma unroll
        for (int j = 0; j < 4; j++)
#pragma unroll
            for (int q = 0; q < 4; q++) acc[i][j][q] = 0.f;

    int a_row = wm * 64 + ((lane >> 3) & 1) * 8 + (lane & 7);
    int a_kb  = (lane >> 4) * 16;
    int b_row = wn * 32 + (lane >> 4) * 8 + (lane & 7);
    int b_kb  = ((lane >> 3) & 1) * 16;

#pragma unroll
    for (int k = 0; k < 4; k++) {
        int kb = k * 32;
        uint32_t af[4][4], bh[8], bl[8];
#pragma unroll
        for (int i = 0; i < 4; i++)
            ldsm4(af[i], sb + SMA_PHI + SWZ128((uint32_t)((a_row + i * 16) * 128 + a_kb + kb)));
        ldsm4(bh,     sb + SMA_RHI + SWZ128((uint32_t)(b_row * 128 + b_kb + kb)));
        ldsm4(bh + 4, sb + SMA_RHI + SWZ128((uint32_t)((b_row + 16) * 128 + b_kb + kb)));
        ldsm4(bl,     sb + SMA_RLO + SWZ128((uint32_t)(b_row * 128 + b_kb + kb)));
        ldsm4(bl + 4, sb + SMA_RLO + SWZ128((uint32_t)((b_row + 16) * 128 + b_kb + kb)));
#pragma unroll
        for (int i = 0; i < 4; i++)
#pragma unroll
            for (int j = 0; j < 4; j++) {
                mma_bf16(acc[i][j], af[i], &bh[j * 2]);
                mma_bf16(acc[i][j], af[i], &bl[j * 2]);
            }
#pragma unroll
        for (int i = 0; i < 4; i++)
            ldsm4(af[i], sb + SMA_PLO + SWZ128((uint32_t)((a_row + i * 16) * 128 + a_kb + kb)));
#pragma unroll
        for (int i = 0; i < 4; i++)
#pragma unroll
            for (int j = 0; j < 4; j++)
                mma_bf16(acc[i][j], af[i], &bh[j * 2]);
    }

    // epilogue: finalize acc with +ci+cj, direct-store tile
    const float* cjs = (const float*)(smem + SMA_CJ);
    int rb = wm * 64 + (lane >> 2);        // local row base
    int cb = wn * 32 + (lane & 3) * 2;     // local col base
#pragma unroll
    for (int i = 0; i < 4; i++) {
#pragma unroll
        for (int h = 0; h < 2; h++) {
            int lrow = rb + i * 16 + h * 8;
            int grow = row0 + lrow;
            float ci = __ldg(&c[min(grow, n - 1)]);
#pragma unroll
            for (int j = 0; j < 4; j++) {
                int lcol = cb + j * 8;
                acc[i][j][h * 2 + 0] += ci + cjs[lcol];
                acc[i][j][h * 2 + 1] += ci + cjs[lcol + 1];
            }
            if (grow < n) {
                float* dst = adj + (size_t)grow * n;
#pragma unroll
                for (int j = 0; j < 4; j++) {
                    int gcol = col0 + cb + j * 8;
                    if (gcol < n) {
                        float2 o = make_float2(acc[i][j][h * 2], acc[i][j][h * 2 + 1]);
                        __stcs((float2*)(dst + gcol), o);
                    }
                }
            }
        }
    }

    // mirror store for off-diagonal tiles: adj[col0+c][row0+r] = T[r][c]
    if (bi != bj) {
        float* Tsm = (float*)smem;  // [128][TPAD], reuses operand tiles + cj
        __syncthreads();            // all cj/operand reads done
#pragma unroll
        for (int i = 0; i < 4; i++)
#pragma unroll
            for (int h = 0; h < 2; h++) {
                int lrow = rb + i * 16 + h * 8;
#pragma unroll
                for (int j = 0; j < 4; j++) {
                    int lcol = cb + j * 8;
                    Tsm[(size_t)lcol * TPAD + lrow] = acc[i][j][h * 2];
                    Tsm[(size_t)(lcol + 1) * TPAD + lrow] = acc[i][j][h * 2 + 1];
                }
            }
        __syncthreads();
        // warp wid stores mirror rows c = s*8 + wid, lane covers 4 cols
        int gcol_m = row0 + lane * 4;   // mirror column base (16B-aligned, n%4==0)
        if (gcol_m < n) {
#pragma unroll
            for (int s = 0; s < 16; s++) {
                int cc = s * 8 + wid;
                int grow_m = col0 + cc;
                if (grow_m < n) {
                    float4 v = *(float4*)&Tsm[(size_t)cc * TPAD + lane * 4];
                    __stcs((float4*)(adj + (size_t)grow_m * n + gcol_m), v);
                }
            }
        }
    }
}

// ---------------- launcher -----------------------------------------------------
extern "C" void kernel_launch(void* const* d_in, const int* in_sizes, int n_in,
                              void* d_out, int out_size) {
    const float* x       = (const float*)d_in[0];
    const void*  ei      = d_in[1];
    const float* enc_W1  = (const float*)d_in[2];
    const float* enc_b1  = (const float*)d_in[3];
    const float* enc_W2  = (const float*)d_in[4];
    const float* enc_b2  = (const float*)d_in[5];
    const float* attr_W1 = (const float*)d_in[6];
    const float* attr_b1 = (const float*)d_in[7];
    const float* attr_W2 = (const float*)d_in[8];
    const float* attr_b2 = (const float*)d_in[9];
    const float* Ws      = (const float*)d_in[10];
    const float* bs      = (const float*)d_in[11];
    float* out = (float*)d_out;

    int E = in_sizes[1] / 2;

    void* sp = nullptr;
    cudaGetSymbolAddress(&sp, d_scratch);
    float* scr = (float*)sp;
    float* B0 = scr + OFF_B0;   float* H1 = scr + OFF_H1;
    float* Q  = scr + OFF_Q;    float* H  = scr + OFF_H;
    float* R  = scr + OFF_R;    float* X1 = scr + OFF_X1;
    float* S  = scr + OFF_S;    float* P  = scr + OFF_P;
    float2* EP = (float2*)(scr + OFF_EPACK);
    float* G  = scr + OFF_G;    float* V  = scr + OFF_V;
    float* BB = scr + OFF_BB;   float* C  = scr + OFF_C;
    float* DINV = scr + OFF_DINV;
    float* SELFC = scr + OFF_SELFC;
    int* OFFS = (int*)(scr + OFF_OFFS);
    int* CUR  = (int*)(scr + OFF_CUR);
    int* CNT  = (int*)(scr + OFF_CNT);
    int* FLAG = (int*)(scr + OFF_FLAG);

    __nv_bfloat16* RHI = (__nv_bfloat16*)(scr + OFF_B0);
    __nv_bfloat16* RLO = (__nv_bfloat16*)(scr + OFF_B0 + 320000);
    __nv_bfloat16* PHI = (__nv_bfloat16*)(scr + OFF_H1);
    __nv_bfloat16* PLO = (__nv_bfloat16*)(scr + OFF_H1 + 320000);

    cudaFuncSetAttribute(k_adj, cudaFuncAttributeMaxDynamicSharedMemorySize, SMA_TOTAL);

    // graph build
    k_init<<<(NN + 255) / 256, 256>>>(ei, CNT, FLAG, NN);
    k_hist<<<(E + 255) / 256, 256>>>(ei, E, FLAG, CNT);
    k_scan<<<1, 1024>>>(CNT, OFFS, CUR, DINV, SELFC, NN);
    k_scatter<<<(E + 255) / 256, 256>>>(ei, E, FLAG, DINV, CUR, EP);

    dim3 gemm_grid1(1, 157), gemm_grid4(4, 157);
    int prop_blocks = (NN * 32 + 255) / 256;

    // encoder
    k_gemm<<<gemm_grid1, 256>>>(x, enc_W1, nullptr, B0, NN, 64, 256, 0);
    k_prop<<<prop_blocks, 256>>>(B0, H1, EP, OFFS, SELFC, enc_b1, 1, NN);
    k_prop<<<prop_blocks, 256>>>(H1, Q, EP, OFFS, SELFC, nullptr, 0, NN);
    k_gemm<<<gemm_grid1, 256>>>(Q, enc_W2, enc_b2, H, NN, 64, 64, 0);
    k_prop<<<prop_blocks, 256>>>(H, R, EP, OFFS, SELFC, nullptr, 0, NN);

    // attribute decoder
    k_gemm<<<gemm_grid1, 256>>>(R, attr_W1, attr_b1, X1, NN, 64, 64, 1);
    k_prop<<<prop_blocks, 256>>>(X1, S, EP, OFFS, SELFC, nullptr, 0, NN);
    k_gemm<<<gemm_grid4, 256>>>(S, attr_W2, attr_b2, out, NN, 256, 64, 0);

    // structure decoder via Gram factorization
    k_gram<<<16, 256>>>(Ws, bs, G, V, BB);
    k_gemm<<<gemm_grid1, 256>>>(R, G, nullptr, P, NN, 64, 64, 0);
    k_c<<<prop_blocks, 256>>>(R, V, BB, C, NN);

    // split to bf16 hi/lo (both R and P in one kernel)
    k_split2<<<(2 * NN * 64 + 255) / 256, 256>>>(R, P, RHI, RLO, PHI, PLO, NN * 64);

    // adj lower triangle + mirror
    int nb = (NN + 127) / 128;
    int ntile = nb * (nb + 1) / 2;
    k_adj<<<ntile, 256, SMA_TOTAL>>>(PHI, PLO, RHI, RLO, C,
                                     out + (size_t)NN * INDIM, NN);
}